// round 16
// baseline (speedup 1.0000x reference)
#include <cuda_runtime.h>
#include <cuda_fp16.h>
#include <math.h>
#include <stdint.h>

#define T_TOK 8192
#define D_DIM 1024
#define I_DIM 2816
#define E_NUM 16
#define NSLOT (T_TOK * 2)
#define BM 128
#define BN 64
#define BK 32
#define NSTAGE 4
#define MAX_MT (NSLOT / BM + E_NUM)   // 144

#define WQ4   ((size_t)E_NUM * D_DIM * I_DIM / 4)   // float4 per weight tensor
#define ZQ4   ((size_t)T_TOK * D_DIM / 4)           // float4 of output
#define HEXP  8                                      // experts per conv half
#define HQ4   ((size_t)HEXP * D_DIM * I_DIM / 4)    // float4 per half per tensor
#define HBLK  ((int)(HQ4 / 256))                    // 22528
#define HMT   (NSLOT / BM + HEXP)                   // 136: worst-case m-tiles per half

// ================= static device scratch =================
__device__ float    g_probs[T_TOK * E_NUM];
__device__ int      g_topk_idx[NSLOT];
__device__ float    g_topk_w[NSLOT];
__device__ int      g_counts[E_NUM];
__device__ int      g_offsets[E_NUM + 1];
__device__ int      g_cursor[E_NUM];
__device__ int      g_mtile_prefix[E_NUM + 1];
__device__ int      g_slot_token[NSLOT];
__device__ float    g_slot_w[NSLOT];
__device__ float    g_gwt[E_NUM * D_DIM];           // transposed gate weights

__device__ uint16_t g_xh [(size_t)T_TOK * D_DIM];
__device__ uint16_t g_Wgh[(size_t)E_NUM * D_DIM * I_DIM];
__device__ uint16_t g_Wuh[(size_t)E_NUM * D_DIM * I_DIM];
__device__ uint16_t g_Wdh[(size_t)E_NUM * I_DIM * D_DIM];
__device__ uint16_t g_H  [(size_t)NSLOT * I_DIM];

// ================= helpers =================
__device__ __forceinline__ uint32_t f2h2(float lo, float hi) {
    uint32_t r;
    asm("cvt.rn.f16x2.f32 %0, %1, %2;" : "=r"(r) : "f"(hi), "f"(lo));
    return r;
}
__device__ __forceinline__ uint32_t smem_u32(const void* p) {
    uint32_t a;
    asm("{ .reg .u64 t; cvta.to.shared.u64 t, %1; cvt.u32.u64 %0, t; }" : "=r"(a) : "l"(p));
    return a;
}
__device__ __forceinline__ void red_add(float* p, float v) {
    asm volatile("red.global.add.f32 [%0], %1;" :: "l"(p), "f"(v) : "memory");
}
#define CP_ASYNC16(dst, src, sz) \
    asm volatile("cp.async.cg.shared.global [%0], [%1], 16, %2;" \
                 :: "r"(dst), "l"(src), "r"(sz) : "memory")
#define CP_COMMIT() asm volatile("cp.async.commit_group;" ::: "memory")
#define CP_WAIT(n)  asm volatile("cp.async.wait_group %0;" :: "n"(n) : "memory")
#define LDSM_X4(r0, r1, r2, r3, addr) \
    asm volatile("ldmatrix.sync.aligned.m8n8.x4.shared.b16 {%0,%1,%2,%3}, [%4];" \
                 : "=r"(r0), "=r"(r1), "=r"(r2), "=r"(r3) : "r"(addr))
#define LDSM_X4_T(r0, r1, r2, r3, addr) \
    asm volatile("ldmatrix.sync.aligned.m8n8.x4.trans.shared.b16 {%0,%1,%2,%3}, [%4];" \
                 : "=r"(r0), "=r"(r1), "=r"(r2), "=r"(r3) : "r"(addr))
#define MMA_F16(d, a, b0, b1) \
    asm volatile( \
        "mma.sync.aligned.m16n8k16.row.col.f32.f16.f16.f32 " \
        "{%0,%1,%2,%3}, {%4,%5,%6,%7}, {%8,%9}, {%0,%1,%2,%3};" \
        : "+f"((d)[0]), "+f"((d)[1]), "+f"((d)[2]), "+f"((d)[3]) \
        : "r"((a)[0]), "r"((a)[1]), "r"((a)[2]), "r"((a)[3]), "r"(b0), "r"(b1))

// ================= gate-weight transpose + counts init =================
__global__ void gwt_kernel(const float* __restrict__ gw) {
    int i = blockIdx.x * 256 + threadIdx.x;   // 16384 total
    if (blockIdx.x == 0 && threadIdx.x < E_NUM) g_counts[threadIdx.x] = 0;
    int d = i >> 4, e = i & 15;
    g_gwt[e * D_DIM + d] = gw[i];
}

// ================= Wg+Wu convert for one expert half (side stream) =================
__global__ void conv_wgu_kernel(const float4* __restrict__ Wg,
                                const float4* __restrict__ Wu, int e_lo) {
    const size_t base = (size_t)e_lo * (D_DIM * I_DIM / 4);
    size_t i = (size_t)blockIdx.x * 256 + threadIdx.x;
    if (i < HQ4) {
        size_t j = base + i;
        float4 v = __ldcs(Wg + j);
        __stcs((uint2*)g_Wgh + j, make_uint2(f2h2(v.x, v.y), f2h2(v.z, v.w)));
    } else {
        size_t j = base + (i - HQ4);
        float4 v = __ldcs(Wu + j);
        __stcs((uint2*)g_Wuh + j, make_uint2(f2h2(v.x, v.y), f2h2(v.z, v.w)));
    }
}

// ================= Wd convert + output zero (side stream) =================
__global__ void wdzero_kernel(const float4* __restrict__ Wd, float4* __restrict__ out4) {
    size_t i = (size_t)blockIdx.x * 256 + threadIdx.x;
    if (i < WQ4) {
        float4 v = __ldcs(Wd + i);
        __stcs((uint2*)g_Wdh + i, make_uint2(f2h2(v.x, v.y), f2h2(v.z, v.w)));
    } else {
        size_t j = i - WQ4;
        if (j < ZQ4) out4[j] = make_float4(0.f, 0.f, 0.f, 0.f);
    }
}

// ================= router: warp-per-token, coalesced gwt, + x -> fp16 =================
__global__ __launch_bounds__(256)
void router_kernel(const float* __restrict__ x) {
    const int lane = threadIdx.x & 31;
    const int t = blockIdx.x * 8 + (threadIdx.x >> 5);
    const float4* xr4 = (const float4*)(x + (size_t)t * D_DIM);
    uint2* xhr = (uint2*)(g_xh + (size_t)t * D_DIM);
    const float4* gwt4 = (const float4*)g_gwt;

    float acc[E_NUM];
#pragma unroll
    for (int e = 0; e < E_NUM; e++) acc[e] = 0.f;

#pragma unroll
    for (int i = 0; i < D_DIM / 128; i++) {
        float4 xv = xr4[i * 32 + lane];
        xhr[i * 32 + lane] = make_uint2(f2h2(xv.x, xv.y), f2h2(xv.z, xv.w));
#pragma unroll
        for (int e = 0; e < E_NUM; e++) {
            float4 g = gwt4[e * (D_DIM / 4) + i * 32 + lane];
            float s = fmaf(xv.x, g.x, fmaf(xv.y, g.y, fmaf(xv.z, g.z, xv.w * g.w)));
            acc[e] += s;
        }
    }
#pragma unroll
    for (int e = 0; e < E_NUM; e++)
#pragma unroll
        for (int off = 16; off > 0; off >>= 1)
            acc[e] += __shfl_down_sync(0xffffffffu, acc[e], off);

    if (lane == 0) {
        float m = acc[0];
#pragma unroll
        for (int e = 1; e < E_NUM; e++) m = fmaxf(m, acc[e]);
        float p[E_NUM], sum = 0.f;
#pragma unroll
        for (int e = 0; e < E_NUM; e++) { p[e] = expf(acc[e] - m); sum += p[e]; }
        float inv = 1.f / sum;
#pragma unroll
        for (int e = 0; e < E_NUM; e++) { p[e] *= inv; g_probs[t * E_NUM + e] = p[e]; }
        int i0 = 0;
#pragma unroll
        for (int e = 1; e < E_NUM; e++) if (p[e] > p[i0]) i0 = e;
        int i1 = (i0 == 0) ? 1 : 0;
#pragma unroll
        for (int e = 0; e < E_NUM; e++) if (e != i0 && p[e] > p[i1]) i1 = e;
        float wn = p[i0] + p[i1];
        g_topk_idx[t * 2 + 0] = i0;
        g_topk_idx[t * 2 + 1] = i1;
        g_topk_w[t * 2 + 0] = p[i0] / wn;
        g_topk_w[t * 2 + 1] = p[i1] / wn;
        atomicAdd(&g_counts[i0], 1);
        atomicAdd(&g_counts[i1], 1);
    }
}

__global__ void offsets_kernel() {
    if (threadIdx.x == 0) {
        int o = 0, mt = 0;
        g_mtile_prefix[0] = 0;
        for (int e = 0; e < E_NUM; e++) {
            g_offsets[e] = o;
            o += g_counts[e];
            mt += (g_counts[e] + BM - 1) / BM;
            g_mtile_prefix[e + 1] = mt;
            g_cursor[e] = 0;
        }
        g_offsets[E_NUM] = o;
    }
}

__global__ void scatter_pos_kernel() {
    int idx = blockIdx.x * 256 + threadIdx.x;
    if (idx >= NSLOT) return;
    int e = g_topk_idx[idx];
    int pos = g_offsets[e] + atomicAdd(&g_cursor[e], 1);
    g_slot_token[pos] = idx >> 1;
    g_slot_w[pos]     = g_topk_w[idx];
}

// SMEM formats: A row r (64B): chunk c at r*64 + 16*(c ^ ((r>>1)&3)).
//               B k-row (128B): chunk c at k*128 + 16*(c ^ (k&7)).

// ================= FFN1 (expert range): H = silu(X Wg) * (X Wu) =================
__global__ __launch_bounds__(128, 2)
void ffn1_kernel(int e_lo, int e_hi) {
    extern __shared__ __align__(16) uint8_t smem[];
    const uint32_t sbase = smem_u32(smem);   // per stage 16KB: A@0, Bg@8192, Bu@12288

    const int mb = g_mtile_prefix[e_lo] + blockIdx.x;
    if (mb >= g_mtile_prefix[e_hi]) return;
    const int nb = blockIdx.y;
    int e = e_lo;
    while (mb >= g_mtile_prefix[e + 1]) e++;
    const int m0   = g_offsets[e] + (mb - g_mtile_prefix[e]) * BM;
    const int mmax = g_offsets[e + 1];

    const int tid = threadIdx.x, lane = tid & 31, wid = tid >> 5;
    const int wm = wid >> 1, wn = wid & 1;

    const int rbase = tid >> 2, chA = tid & 3;
    const int kbB = tid >> 3, chB = tid & 7;
    const char* aSrc[4];
    uint32_t    aDst[4], aSz[4];
#pragma unroll
    for (int rr = 0; rr < 4; rr++) {
        int row = rbase + 32 * rr;
        int gr  = m0 + row;
        int ok  = gr < mmax;
        int tok = ok ? g_slot_token[gr] : 0;
        aSrc[rr] = (const char*)g_xh + (size_t)tok * D_DIM * 2 + chA * 16;
        aDst[rr] = row * 64 + 16 * (chA ^ ((row >> 1) & 3));
        aSz[rr]  = ok ? 16u : 0u;
    }
    const char* gSrc[2];
    const char* uSrc[2];
    uint32_t    bDst[2];
#pragma unroll
    for (int i = 0; i < 2; i++) {
        int k = kbB + 16 * i;
        size_t off = (((size_t)e * D_DIM + k) * I_DIM + (size_t)nb * BN) * 2 + chB * 16;
        gSrc[i] = (const char*)g_Wgh + off;
        uSrc[i] = (const char*)g_Wuh + off;
        bDst[i] = k * 128 + 16 * (chB ^ (k & 7));
    }

#define FFN1_ISSUE(BUF, KC)                                                     \
    do {                                                                        \
        uint32_t sb = sbase + (BUF) * 16384;                                    \
        _Pragma("unroll")                                                       \
        for (int rr = 0; rr < 4; rr++)                                          \
            CP_ASYNC16(sb + aDst[rr], aSrc[rr] + (size_t)(KC) * 64, aSz[rr]);   \
        _Pragma("unroll")                                                       \
        for (int i = 0; i < 2; i++) {                                           \
            size_t ko = (size_t)(KC) * BK * I_DIM * 2;                          \
            CP_ASYNC16(sb + 8192  + bDst[i], gSrc[i] + ko, 16u);                \
            CP_ASYNC16(sb + 12288 + bDst[i], uSrc[i] + ko, 16u);                \
        }                                                                       \
    } while (0)

    float accg[4][4][4], accu[4][4][4];
#pragma unroll
    for (int i = 0; i < 4; i++)
#pragma unroll
        for (int j = 0; j < 4; j++)
#pragma unroll
            for (int k = 0; k < 4; k++) { accg[i][j][k] = 0.f; accu[i][j][k] = 0.f; }

    const int NC = D_DIM / BK;   // 32
#pragma unroll
    for (int s = 0; s < NSTAGE - 1; s++) { FFN1_ISSUE(s, s); CP_COMMIT(); }

    for (int kc = 0; kc < NC; kc++) {
        CP_WAIT(NSTAGE - 2);
        __syncthreads();
        int nk = kc + NSTAGE - 1;
        if (nk < NC) FFN1_ISSUE(nk & (NSTAGE - 1), nk);
        CP_COMMIT();

        const uint32_t abase = sbase + (kc & (NSTAGE - 1)) * 16384;
#pragma unroll
        for (int ks = 0; ks < 2; ks++) {
            uint32_t a[4][4];
#pragma unroll
            for (int mf = 0; mf < 4; mf++) {
                int r  = wm * 64 + mf * 16 + (lane & 15);
                int lc = ks * 2 + (lane >> 4);
                LDSM_X4(a[mf][0], a[mf][1], a[mf][2], a[mf][3],
                        abase + r * 64 + 16 * (lc ^ ((r >> 1) & 3)));
            }
            uint32_t bg[2][4], bu[2][4];
#pragma unroll
            for (int np = 0; np < 2; np++) {
                int k  = ks * 16 + ((lane >> 3) & 1) * 8 + (lane & 7);
                int nl = wn * 32 + np * 16 + (lane >> 4) * 8;
                uint32_t off = k * 128 + 16 * ((nl >> 3) ^ (k & 7));
                LDSM_X4_T(bg[np][0], bg[np][1], bg[np][2], bg[np][3], abase + 8192 + off);
                LDSM_X4_T(bu[np][0], bu[np][1], bu[np][2], bu[np][3], abase + 12288 + off);
            }
#pragma unroll
            for (int mf = 0; mf < 4; mf++)
#pragma unroll
                for (int nf = 0; nf < 4; nf++) {
                    MMA_F16(accg[mf][nf], a[mf], bg[nf >> 1][(nf & 1) * 2],
                            bg[nf >> 1][(nf & 1) * 2 + 1]);
                    MMA_F16(accu[mf][nf], a[mf], bu[nf >> 1][(nf & 1) * 2],
                            bu[nf >> 1][(nf & 1) * 2 + 1]);
                }
        }
    }

#pragma unroll
    for (int mf = 0; mf < 4; mf++) {
        int r0 = m0 + wm * 64 + mf * 16 + (lane >> 2);
        int r1 = r0 + 8;
#pragma unroll
        for (int nf = 0; nf < 4; nf++) {
            int col = nb * BN + wn * 32 + nf * 8 + (lane & 3) * 2;
            if (r0 < mmax) {
                float g0 = accg[mf][nf][0], g1 = accg[mf][nf][1];
                float h0 = g0 / (1.f + expf(-g0)) * accu[mf][nf][0];
                float h1 = g1 / (1.f + expf(-g1)) * accu[mf][nf][1];
                *(uint32_t*)(g_H + (size_t)r0 * I_DIM + col) = f2h2(h0, h1);
            }
            if (r1 < mmax) {
                float g2 = accg[mf][nf][2], g3 = accg[mf][nf][3];
                float h2 = g2 / (1.f + expf(-g2)) * accu[mf][nf][2];
                float h3 = g3 / (1.f + expf(-g3)) * accu[mf][nf][3];
                *(uint32_t*)(g_H + (size_t)r1 * I_DIM + col) = f2h2(h2, h3);
            }
        }
    }
}

// ================= FFN2: out += (H Wd) * slot_w  (nb varies fastest for H reuse) =====
__global__ __launch_bounds__(128, 3)
void ffn2_kernel(float* __restrict__ out) {
    extern __shared__ __align__(16) uint8_t smem[];
    const uint32_t sbase = smem_u32(smem);   // per stage 12KB: A@0, B@8192

    const int mb = blockIdx.y, nb = blockIdx.x;   // nb fastest: A-tile reuse in L2
    if (mb >= g_mtile_prefix[E_NUM]) return;
    int e = 0;
    while (mb >= g_mtile_prefix[e + 1]) e++;
    const int m0   = g_offsets[e] + (mb - g_mtile_prefix[e]) * BM;
    const int mmax = g_offsets[e + 1];

    const int tid = threadIdx.x, lane = tid & 31, wid = tid >> 5;
    const int wm = wid >> 1, wn = wid & 1;

    const int rbase = tid >> 2, chA = tid & 3;
    const int kbB = tid >> 3, chB = tid & 7;
    const char* aSrc[4];
    uint32_t    aDst[4], aSz[4];
#pragma unroll
    for (int rr = 0; rr < 4; rr++) {
        int row = rbase + 32 * rr;
        int gr  = m0 + row;
        int ok  = gr < mmax;
        aSrc[rr] = (const char*)g_H + (size_t)(ok ? gr : 0) * I_DIM * 2 + chA * 16;
        aDst[rr] = row * 64 + 16 * (chA ^ ((row >> 1) & 3));
        aSz[rr]  = ok ? 16u : 0u;
    }
    const char* dSrc[2];
    uint32_t    bDst[2];
#pragma unroll
    for (int i = 0; i < 2; i++) {
        int k = kbB + 16 * i;
        dSrc[i] = (const char*)g_Wdh +
                  (((size_t)e * I_DIM + k) * D_DIM + (size_t)nb * BN) * 2 + chB * 16;
        bDst[i] = k * 128 + 16 * (chB ^ (k & 7));
    }

#define FFN2_ISSUE(BUF, KC)                                                     \
    do {                                                                        \
        uint32_t sb = sbase + (BUF) * 12288;                                    \
        _Pragma("unroll")                                                       \
        for (int rr = 0; rr < 4; rr++)                                          \
            CP_ASYNC16(sb + aDst[rr], aSrc[rr] + (size_t)(KC) * 64, aSz[rr]);   \
        _Pragma("unroll")                                                       \
        for (int i = 0; i < 2; i++)                                             \
            CP_ASYNC16(sb + 8192 + bDst[i],                                     \
                       dSrc[i] + (size_t)(KC) * BK * D_DIM * 2, 16u);           \
    } while (0)

    float acc[4][4][4];
#pragma unroll
    for (int i = 0; i < 4; i++)
#pragma unroll
        for (int j = 0; j < 4; j++)
#pragma unroll
            for (int k = 0; k < 4; k++) acc[i][j][k] = 0.f;

    const int NC = I_DIM / BK;   // 88
#pragma unroll
    for (int s = 0; s < NSTAGE - 1; s++) { FFN2_ISSUE(s, s); CP_COMMIT(); }

    for (int kc = 0; kc < NC; kc++) {
        CP_WAIT(NSTAGE - 2);
        __syncthreads();
        int nk = kc + NSTAGE - 1;
        if (nk < NC) FFN2_ISSUE(nk & (NSTAGE - 1), nk);
        CP_COMMIT();

        const uint32_t abase = sbase + (kc & (NSTAGE - 1)) * 12288;
#pragma unroll
        for (int ks = 0; ks < 2; ks++) {
            uint32_t a[4][4];
#pragma unroll
            for (int mf = 0; mf < 4; mf++) {
                int r  = wm * 64 + mf * 16 + (lane & 15);
                int lc = ks * 2 + (lane >> 4);
                LDSM_X4(a[mf][0], a[mf][1], a[mf][2], a[mf][3],
                        abase + r * 64 + 16 * (lc ^ ((r >> 1) & 3)));
            }
            uint32_t b[2][4];
#pragma unroll
            for (int np = 0; np < 2; np++) {
                int k  = ks * 16 + ((lane >> 3) & 1) * 8 + (lane & 7);
                int nl = wn * 32 + np * 16 + (lane >> 4) * 8;
                LDSM_X4_T(b[np][0], b[np][1], b[np][2], b[np][3],
                          abase + 8192 + k * 128 + 16 * ((nl >> 3) ^ (k & 7)));
            }
#pragma unroll
            for (int mf = 0; mf < 4; mf++)
#pragma unroll
                for (int nf = 0; nf < 4; nf++)
                    MMA_F16(acc[mf][nf], a[mf], b[nf >> 1][(nf & 1) * 2],
                            b[nf >> 1][(nf & 1) * 2 + 1]);
        }
    }

#pragma unroll
    for (int mf = 0; mf < 4; mf++) {
        int r0 = m0 + wm * 64 + mf * 16 + (lane >> 2);
        int r1 = r0 + 8;
        bool ok0 = r0 < mmax, ok1 = r1 < mmax;
        float w0 = ok0 ? g_slot_w[r0] : 0.f;
        float w1 = ok1 ? g_slot_w[r1] : 0.f;
        int tok0 = ok0 ? g_slot_token[r0] : 0;
        int tok1 = ok1 ? g_slot_token[r1] : 0;
#pragma unroll
        for (int nf = 0; nf < 4; nf++) {
            int col = nb * BN + wn * 32 + nf * 8 + (lane & 3) * 2;
            if (ok0) {
                float* p = out + (size_t)tok0 * D_DIM + col;
                red_add(p,     acc[mf][nf][0] * w0);
                red_add(p + 1, acc[mf][nf][1] * w0);
            }
            if (ok1) {
                float* p = out + (size_t)tok1 * D_DIM + col;
                red_add(p,     acc[mf][nf][2] * w1);
                red_add(p + 1, acc[mf][nf][3] * w1);
            }
        }
    }
}

// ================= aux (side stream) =================
__global__ void aux_kernel(float* __restrict__ out, int out_size) {
    __shared__ float red[256];
    __shared__ float esum[E_NUM];
    float part[E_NUM];
#pragma unroll
    for (int e = 0; e < E_NUM; e++) part[e] = 0.f;
    for (int t = threadIdx.x; t < T_TOK; t += 256)
#pragma unroll
        for (int e = 0; e < E_NUM; e++) part[e] += g_probs[t * E_NUM + e];
    for (int e = 0; e < E_NUM; e++) {
        red[threadIdx.x] = part[e];
        __syncthreads();
        for (int off = 128; off > 0; off >>= 1) {
            if (threadIdx.x < off) red[threadIdx.x] += red[threadIdx.x + off];
            __syncthreads();
        }
        if (threadIdx.x == 0) esum[e] = red[0];
        __syncthreads();
    }
    if (threadIdx.x == 0) {
        float aux = 0.f;
        for (int e = 0; e < E_NUM; e++)
            aux += ((float)g_counts[e] / (float)T_TOK) * (esum[e] / (float)T_TOK);
        aux *= 0.01f * (float)E_NUM;
        if (out_size > T_TOK * D_DIM) out[(size_t)T_TOK * D_DIM] = aux;
    }
}

// ================= launch =================
extern "C" void kernel_launch(void* const* d_in, const int* in_sizes, int n_in,
                              void* d_out, int out_size) {
    const float* x      = (const float*)d_in[0];
    const float* gate_w = (const float*)d_in[1];
    const float* Wg     = (const float*)d_in[2];
    const float* Wu     = (const float*)d_in[3];
    const float* Wd     = (const float*)d_in[4];
    float* out = (float*)d_out;

    cudaFuncSetAttribute(ffn1_kernel, cudaFuncAttributeMaxDynamicSharedMemorySize,
                         NSTAGE * 16384);
    cudaFuncSetAttribute(ffn2_kernel, cudaFuncAttributeMaxDynamicSharedMemorySize,
                         NSTAGE * 12288);

    cudaStream_t sA;
    cudaStreamCreateWithFlags(&sA, cudaStreamNonBlocking);
    cudaEvent_t evFork, evW0, evW1, evPre, evA;
    cudaEventCreateWithFlags(&evFork, cudaEventDisableTiming);
    cudaEventCreateWithFlags(&evW0,  cudaEventDisableTiming);
    cudaEventCreateWithFlags(&evW1,  cudaEventDisableTiming);
    cudaEventCreateWithFlags(&evPre, cudaEventDisableTiming);
    cudaEventCreateWithFlags(&evA,   cudaEventDisableTiming);

    // fork side stream FROM the capture origin stream
    cudaEventRecord(evFork, 0);
    cudaStreamWaitEvent(sA, evFork, 0);

    // side stream: conv half 0, conv half 1, Wd convert + out zero
    conv_wgu_kernel<<<2 * HBLK, 256, 0, sA>>>((const float4*)Wg, (const float4*)Wu, 0);
    cudaEventRecord(evW0, sA);
    conv_wgu_kernel<<<2 * HBLK, 256, 0, sA>>>((const float4*)Wg, (const float4*)Wu, HEXP);
    cudaEventRecord(evW1, sA);
    int wz_blocks = (int)((WQ4 + ZQ4 + 255) / 256);
    wdzero_kernel<<<wz_blocks, 256, 0, sA>>>((const float4*)Wd, (float4*)out);

    // main stream: router chain (hidden under the converts)
    gwt_kernel<<<E_NUM * D_DIM / 256, 256>>>(gate_w);
    router_kernel<<<T_TOK / 8, 256>>>(x);
    offsets_kernel<<<1, 32>>>();
    scatter_pos_kernel<<<(NSLOT + 255) / 256, 256>>>();
    cudaEventRecord(evPre, 0);

    // aux rides the side stream (needs router output only)
    cudaStreamWaitEvent(sA, evPre, 0);
    aux_kernel<<<1, 256, 0, sA>>>(out, out_size);
    cudaEventRecord(evA, sA);

    // FFN1 in two expert halves, each gated on its own convert half
    cudaStreamWaitEvent(0, evW0, 0);
    dim3 g1(HMT, I_DIM / BN);   // 136 x 44, early exit beyond half's m-tiles
    ffn1_kernel<<<g1, 128, NSTAGE * 16384>>>(0, HEXP);
    cudaStreamWaitEvent(0, evW1, 0);
    ffn1_kernel<<<g1, 128, NSTAGE * 16384>>>(HEXP, E_NUM);

    // FFN2 joins side stream (Wd + zeroed out + aux ordered before evA)
    cudaStreamWaitEvent(0, evA, 0);
    dim3 g2(D_DIM / BN, MAX_MT);   // 16 x 144, nb fastest
    ffn2_kernel<<<g2, 128, NSTAGE * 12288>>>(out);
}

// round 17
// speedup vs baseline: 1.0160x; 1.0160x over previous
#include <cuda_runtime.h>
#include <cuda_fp16.h>
#include <math.h>
#include <stdint.h>

#define T_TOK 8192
#define D_DIM 1024
#define I_DIM 2816
#define E_NUM 16
#define NSLOT (T_TOK * 2)
#define BM 128
#define BN 64
#define BK 32
#define NSTAGE 4

#define WQ4   ((size_t)E_NUM * D_DIM * I_DIM / 4)   // float4 per weight tensor
#define ZQ4   ((size_t)T_TOK * D_DIM / 4)           // float4 of output
#define HEXP  8                                      // experts per half
#define HQ4   ((size_t)HEXP * D_DIM * I_DIM / 4)    // float4 per half per tensor
#define HBLK  ((int)(HQ4 / 256))                    // 22528
#define HMT   (NSLOT / BM + HEXP)                   // 136: worst-case m-tiles per half

// ================= static device scratch =================
__device__ float    g_probs[T_TOK * E_NUM];
__device__ int      g_topk_idx[NSLOT];
__device__ float    g_topk_w[NSLOT];
__device__ int      g_counts[E_NUM];
__device__ int      g_offsets[E_NUM + 1];
__device__ int      g_cursor[E_NUM];
__device__ int      g_mtile_prefix[E_NUM + 1];
__device__ int      g_slot_token[NSLOT];
__device__ float    g_slot_w[NSLOT];
__device__ float    g_gwt[E_NUM * D_DIM];           // transposed gate weights

__device__ uint16_t g_xh [(size_t)T_TOK * D_DIM];
__device__ uint16_t g_Wgh[(size_t)E_NUM * D_DIM * I_DIM];
__device__ uint16_t g_Wuh[(size_t)E_NUM * D_DIM * I_DIM];
__device__ uint16_t g_Wdh[(size_t)E_NUM * I_DIM * D_DIM];
__device__ uint16_t g_H  [(size_t)NSLOT * I_DIM];

// ================= helpers =================
__device__ __forceinline__ uint32_t f2h2(float lo, float hi) {
    uint32_t r;
    asm("cvt.rn.f16x2.f32 %0, %1, %2;" : "=r"(r) : "f"(hi), "f"(lo));
    return r;
}
__device__ __forceinline__ uint32_t smem_u32(const void* p) {
    uint32_t a;
    asm("{ .reg .u64 t; cvta.to.shared.u64 t, %1; cvt.u32.u64 %0, t; }" : "=r"(a) : "l"(p));
    return a;
}
__device__ __forceinline__ void red_add(float* p, float v) {
    asm volatile("red.global.add.f32 [%0], %1;" :: "l"(p), "f"(v) : "memory");
}
#define CP_ASYNC16(dst, src, sz) \
    asm volatile("cp.async.cg.shared.global [%0], [%1], 16, %2;" \
                 :: "r"(dst), "l"(src), "r"(sz) : "memory")
#define CP_COMMIT() asm volatile("cp.async.commit_group;" ::: "memory")
#define CP_WAIT(n)  asm volatile("cp.async.wait_group %0;" :: "n"(n) : "memory")
#define LDSM_X4(r0, r1, r2, r3, addr) \
    asm volatile("ldmatrix.sync.aligned.m8n8.x4.shared.b16 {%0,%1,%2,%3}, [%4];" \
                 : "=r"(r0), "=r"(r1), "=r"(r2), "=r"(r3) : "r"(addr))
#define LDSM_X4_T(r0, r1, r2, r3, addr) \
    asm volatile("ldmatrix.sync.aligned.m8n8.x4.trans.shared.b16 {%0,%1,%2,%3}, [%4];" \
                 : "=r"(r0), "=r"(r1), "=r"(r2), "=r"(r3) : "r"(addr))
#define MMA_F16(d, a, b0, b1) \
    asm volatile( \
        "mma.sync.aligned.m16n8k16.row.col.f32.f16.f16.f32 " \
        "{%0,%1,%2,%3}, {%4,%5,%6,%7}, {%8,%9}, {%0,%1,%2,%3};" \
        : "+f"((d)[0]), "+f"((d)[1]), "+f"((d)[2]), "+f"((d)[3]) \
        : "r"((a)[0]), "r"((a)[1]), "r"((a)[2]), "r"((a)[3]), "r"(b0), "r"(b1))

// ================= gate-weight transpose + counts init =================
__global__ void gwt_kernel(const float* __restrict__ gw) {
    int i = blockIdx.x * 256 + threadIdx.x;   // 16384 total
    if (blockIdx.x == 0 && threadIdx.x < E_NUM) g_counts[threadIdx.x] = 0;
    int d = i >> 4, e = i & 15;
    g_gwt[e * D_DIM + d] = gw[i];
}

// ================= Wg+Wu convert for one expert half (side stream) =================
__global__ void conv_wgu_kernel(const float4* __restrict__ Wg,
                                const float4* __restrict__ Wu, int e_lo) {
    const size_t base = (size_t)e_lo * (D_DIM * I_DIM / 4);
    size_t i = (size_t)blockIdx.x * 256 + threadIdx.x;
    if (i < HQ4) {
        size_t j = base + i;
        float4 v = __ldcs(Wg + j);
        __stcs((uint2*)g_Wgh + j, make_uint2(f2h2(v.x, v.y), f2h2(v.z, v.w)));
    } else {
        size_t j = base + (i - HQ4);
        float4 v = __ldcs(Wu + j);
        __stcs((uint2*)g_Wuh + j, make_uint2(f2h2(v.x, v.y), f2h2(v.z, v.w)));
    }
}

// ================= Wd convert + output zero (side stream) =================
__global__ void wdzero_kernel(const float4* __restrict__ Wd, float4* __restrict__ out4) {
    size_t i = (size_t)blockIdx.x * 256 + threadIdx.x;
    if (i < WQ4) {
        float4 v = __ldcs(Wd + i);
        __stcs((uint2*)g_Wdh + i, make_uint2(f2h2(v.x, v.y), f2h2(v.z, v.w)));
    } else {
        size_t j = i - WQ4;
        if (j < ZQ4) out4[j] = make_float4(0.f, 0.f, 0.f, 0.f);
    }
}

// ================= router: warp-per-token, coalesced gwt, + x -> fp16 =================
__global__ __launch_bounds__(256)
void router_kernel(const float* __restrict__ x) {
    const int lane = threadIdx.x & 31;
    const int t = blockIdx.x * 8 + (threadIdx.x >> 5);
    const float4* xr4 = (const float4*)(x + (size_t)t * D_DIM);
    uint2* xhr = (uint2*)(g_xh + (size_t)t * D_DIM);
    const float4* gwt4 = (const float4*)g_gwt;

    float acc[E_NUM];
#pragma unroll
    for (int e = 0; e < E_NUM; e++) acc[e] = 0.f;

#pragma unroll
    for (int i = 0; i < D_DIM / 128; i++) {
        float4 xv = xr4[i * 32 + lane];
        xhr[i * 32 + lane] = make_uint2(f2h2(xv.x, xv.y), f2h2(xv.z, xv.w));
#pragma unroll
        for (int e = 0; e < E_NUM; e++) {
            float4 g = gwt4[e * (D_DIM / 4) + i * 32 + lane];
            float s = fmaf(xv.x, g.x, fmaf(xv.y, g.y, fmaf(xv.z, g.z, xv.w * g.w)));
            acc[e] += s;
        }
    }
#pragma unroll
    for (int e = 0; e < E_NUM; e++)
#pragma unroll
        for (int off = 16; off > 0; off >>= 1)
            acc[e] += __shfl_down_sync(0xffffffffu, acc[e], off);

    if (lane == 0) {
        float m = acc[0];
#pragma unroll
        for (int e = 1; e < E_NUM; e++) m = fmaxf(m, acc[e]);
        float p[E_NUM], sum = 0.f;
#pragma unroll
        for (int e = 0; e < E_NUM; e++) { p[e] = expf(acc[e] - m); sum += p[e]; }
        float inv = 1.f / sum;
#pragma unroll
        for (int e = 0; e < E_NUM; e++) { p[e] *= inv; g_probs[t * E_NUM + e] = p[e]; }
        int i0 = 0;
#pragma unroll
        for (int e = 1; e < E_NUM; e++) if (p[e] > p[i0]) i0 = e;
        int i1 = (i0 == 0) ? 1 : 0;
#pragma unroll
        for (int e = 0; e < E_NUM; e++) if (e != i0 && p[e] > p[i1]) i1 = e;
        float wn = p[i0] + p[i1];
        g_topk_idx[t * 2 + 0] = i0;
        g_topk_idx[t * 2 + 1] = i1;
        g_topk_w[t * 2 + 0] = p[i0] / wn;
        g_topk_w[t * 2 + 1] = p[i1] / wn;
        atomicAdd(&g_counts[i0], 1);
        atomicAdd(&g_counts[i1], 1);
    }
}

__global__ void offsets_kernel() {
    if (threadIdx.x == 0) {
        int o = 0, mt = 0;
        g_mtile_prefix[0] = 0;
        for (int e = 0; e < E_NUM; e++) {
            g_offsets[e] = o;
            o += g_counts[e];
            mt += (g_counts[e] + BM - 1) / BM;
            g_mtile_prefix[e + 1] = mt;
            g_cursor[e] = 0;
        }
        g_offsets[E_NUM] = o;
    }
}

__global__ void scatter_pos_kernel() {
    int idx = blockIdx.x * 256 + threadIdx.x;
    if (idx >= NSLOT) return;
    int e = g_topk_idx[idx];
    int pos = g_offsets[e] + atomicAdd(&g_cursor[e], 1);
    g_slot_token[pos] = idx >> 1;
    g_slot_w[pos]     = g_topk_w[idx];
}

// SMEM formats: A row r (64B): chunk c at r*64 + 16*(c ^ ((r>>1)&3)).
//               B k-row (128B): chunk c at k*128 + 16*(c ^ (k&7)).

// ================= FFN1 (expert range): H = silu(X Wg) * (X Wu) =================
__global__ __launch_bounds__(128, 2)
void ffn1_kernel(int e_lo, int e_hi) {
    extern __shared__ __align__(16) uint8_t smem[];
    const uint32_t sbase = smem_u32(smem);   // per stage 16KB: A@0, Bg@8192, Bu@12288

    const int mb = g_mtile_prefix[e_lo] + blockIdx.x;
    if (mb >= g_mtile_prefix[e_hi]) return;
    const int nb = blockIdx.y;
    int e = e_lo;
    while (mb >= g_mtile_prefix[e + 1]) e++;
    const int m0   = g_offsets[e] + (mb - g_mtile_prefix[e]) * BM;
    const int mmax = g_offsets[e + 1];

    const int tid = threadIdx.x, lane = tid & 31, wid = tid >> 5;
    const int wm = wid >> 1, wn = wid & 1;

    const int rbase = tid >> 2, chA = tid & 3;
    const int kbB = tid >> 3, chB = tid & 7;
    const char* aSrc[4];
    uint32_t    aDst[4], aSz[4];
#pragma unroll
    for (int rr = 0; rr < 4; rr++) {
        int row = rbase + 32 * rr;
        int gr  = m0 + row;
        int ok  = gr < mmax;
        int tok = ok ? g_slot_token[gr] : 0;
        aSrc[rr] = (const char*)g_xh + (size_t)tok * D_DIM * 2 + chA * 16;
        aDst[rr] = row * 64 + 16 * (chA ^ ((row >> 1) & 3));
        aSz[rr]  = ok ? 16u : 0u;
    }
    const char* gSrc[2];
    const char* uSrc[2];
    uint32_t    bDst[2];
#pragma unroll
    for (int i = 0; i < 2; i++) {
        int k = kbB + 16 * i;
        size_t off = (((size_t)e * D_DIM + k) * I_DIM + (size_t)nb * BN) * 2 + chB * 16;
        gSrc[i] = (const char*)g_Wgh + off;
        uSrc[i] = (const char*)g_Wuh + off;
        bDst[i] = k * 128 + 16 * (chB ^ (k & 7));
    }

#define FFN1_ISSUE(BUF, KC)                                                     \
    do {                                                                        \
        uint32_t sb = sbase + (BUF) * 16384;                                    \
        _Pragma("unroll")                                                       \
        for (int rr = 0; rr < 4; rr++)                                          \
            CP_ASYNC16(sb + aDst[rr], aSrc[rr] + (size_t)(KC) * 64, aSz[rr]);   \
        _Pragma("unroll")                                                       \
        for (int i = 0; i < 2; i++) {                                           \
            size_t ko = (size_t)(KC) * BK * I_DIM * 2;                          \
            CP_ASYNC16(sb + 8192  + bDst[i], gSrc[i] + ko, 16u);                \
            CP_ASYNC16(sb + 12288 + bDst[i], uSrc[i] + ko, 16u);                \
        }                                                                       \
    } while (0)

    float accg[4][4][4], accu[4][4][4];
#pragma unroll
    for (int i = 0; i < 4; i++)
#pragma unroll
        for (int j = 0; j < 4; j++)
#pragma unroll
            for (int k = 0; k < 4; k++) { accg[i][j][k] = 0.f; accu[i][j][k] = 0.f; }

    const int NC = D_DIM / BK;   // 32
#pragma unroll
    for (int s = 0; s < NSTAGE - 1; s++) { FFN1_ISSUE(s, s); CP_COMMIT(); }

    for (int kc = 0; kc < NC; kc++) {
        CP_WAIT(NSTAGE - 2);
        __syncthreads();
        int nk = kc + NSTAGE - 1;
        if (nk < NC) FFN1_ISSUE(nk & (NSTAGE - 1), nk);
        CP_COMMIT();

        const uint32_t abase = sbase + (kc & (NSTAGE - 1)) * 16384;
#pragma unroll
        for (int ks = 0; ks < 2; ks++) {
            uint32_t a[4][4];
#pragma unroll
            for (int mf = 0; mf < 4; mf++) {
                int r  = wm * 64 + mf * 16 + (lane & 15);
                int lc = ks * 2 + (lane >> 4);
                LDSM_X4(a[mf][0], a[mf][1], a[mf][2], a[mf][3],
                        abase + r * 64 + 16 * (lc ^ ((r >> 1) & 3)));
            }
            uint32_t bg[2][4], bu[2][4];
#pragma unroll
            for (int np = 0; np < 2; np++) {
                int k  = ks * 16 + ((lane >> 3) & 1) * 8 + (lane & 7);
                int nl = wn * 32 + np * 16 + (lane >> 4) * 8;
                uint32_t off = k * 128 + 16 * ((nl >> 3) ^ (k & 7));
                LDSM_X4_T(bg[np][0], bg[np][1], bg[np][2], bg[np][3], abase + 8192 + off);
                LDSM_X4_T(bu[np][0], bu[np][1], bu[np][2], bu[np][3], abase + 12288 + off);
            }
#pragma unroll
            for (int mf = 0; mf < 4; mf++)
#pragma unroll
                for (int nf = 0; nf < 4; nf++) {
                    MMA_F16(accg[mf][nf], a[mf], bg[nf >> 1][(nf & 1) * 2],
                            bg[nf >> 1][(nf & 1) * 2 + 1]);
                    MMA_F16(accu[mf][nf], a[mf], bu[nf >> 1][(nf & 1) * 2],
                            bu[nf >> 1][(nf & 1) * 2 + 1]);
                }
        }
    }

#pragma unroll
    for (int mf = 0; mf < 4; mf++) {
        int r0 = m0 + wm * 64 + mf * 16 + (lane >> 2);
        int r1 = r0 + 8;
#pragma unroll
        for (int nf = 0; nf < 4; nf++) {
            int col = nb * BN + wn * 32 + nf * 8 + (lane & 3) * 2;
            if (r0 < mmax) {
                float g0 = accg[mf][nf][0], g1 = accg[mf][nf][1];
                float h0 = g0 / (1.f + expf(-g0)) * accu[mf][nf][0];
                float h1 = g1 / (1.f + expf(-g1)) * accu[mf][nf][1];
                *(uint32_t*)(g_H + (size_t)r0 * I_DIM + col) = f2h2(h0, h1);
            }
            if (r1 < mmax) {
                float g2 = accg[mf][nf][2], g3 = accg[mf][nf][3];
                float h2 = g2 / (1.f + expf(-g2)) * accu[mf][nf][2];
                float h3 = g3 / (1.f + expf(-g3)) * accu[mf][nf][3];
                *(uint32_t*)(g_H + (size_t)r1 * I_DIM + col) = f2h2(h2, h3);
            }
        }
    }
}

// ================= FFN2 (expert range): out += (H Wd) * slot_w =================
__global__ __launch_bounds__(128, 3)
void ffn2_kernel(float* __restrict__ out, int e_lo, int e_hi) {
    extern __shared__ __align__(16) uint8_t smem[];
    const uint32_t sbase = smem_u32(smem);   // per stage 12KB: A@0, B@8192

    const int mb = g_mtile_prefix[e_lo] + blockIdx.x;   // mb fastest (R15 order)
    if (mb >= g_mtile_prefix[e_hi]) return;
    const int nb = blockIdx.y;
    int e = e_lo;
    while (mb >= g_mtile_prefix[e + 1]) e++;
    const int m0   = g_offsets[e] + (mb - g_mtile_prefix[e]) * BM;
    const int mmax = g_offsets[e + 1];

    const int tid = threadIdx.x, lane = tid & 31, wid = tid >> 5;
    const int wm = wid >> 1, wn = wid & 1;

    const int rbase = tid >> 2, chA = tid & 3;
    const int kbB = tid >> 3, chB = tid & 7;
    const char* aSrc[4];
    uint32_t    aDst[4], aSz[4];
#pragma unroll
    for (int rr = 0; rr < 4; rr++) {
        int row = rbase + 32 * rr;
        int gr  = m0 + row;
        int ok  = gr < mmax;
        aSrc[rr] = (const char*)g_H + (size_t)(ok ? gr : 0) * I_DIM * 2 + chA * 16;
        aDst[rr] = row * 64 + 16 * (chA ^ ((row >> 1) & 3));
        aSz[rr]  = ok ? 16u : 0u;
    }
    const char* dSrc[2];
    uint32_t    bDst[2];
#pragma unroll
    for (int i = 0; i < 2; i++) {
        int k = kbB + 16 * i;
        dSrc[i] = (const char*)g_Wdh +
                  (((size_t)e * I_DIM + k) * D_DIM + (size_t)nb * BN) * 2 + chB * 16;
        bDst[i] = k * 128 + 16 * (chB ^ (k & 7));
    }

#define FFN2_ISSUE(BUF, KC)                                                     \
    do {                                                                        \
        uint32_t sb = sbase + (BUF) * 12288;                                    \
        _Pragma("unroll")                                                       \
        for (int rr = 0; rr < 4; rr++)                                          \
            CP_ASYNC16(sb + aDst[rr], aSrc[rr] + (size_t)(KC) * 64, aSz[rr]);   \
        _Pragma("unroll")                                                       \
        for (int i = 0; i < 2; i++)                                             \
            CP_ASYNC16(sb + 8192 + bDst[i],                                     \
                       dSrc[i] + (size_t)(KC) * BK * D_DIM * 2, 16u);           \
    } while (0)

    float acc[4][4][4];
#pragma unroll
    for (int i = 0; i < 4; i++)
#pragma unroll
        for (int j = 0; j < 4; j++)
#pragma unroll
            for (int k = 0; k < 4; k++) acc[i][j][k] = 0.f;

    const int NC = I_DIM / BK;   // 88
#pragma unroll
    for (int s = 0; s < NSTAGE - 1; s++) { FFN2_ISSUE(s, s); CP_COMMIT(); }

    for (int kc = 0; kc < NC; kc++) {
        CP_WAIT(NSTAGE - 2);
        __syncthreads();
        int nk = kc + NSTAGE - 1;
        if (nk < NC) FFN2_ISSUE(nk & (NSTAGE - 1), nk);
        CP_COMMIT();

        const uint32_t abase = sbase + (kc & (NSTAGE - 1)) * 12288;
#pragma unroll
        for (int ks = 0; ks < 2; ks++) {
            uint32_t a[4][4];
#pragma unroll
            for (int mf = 0; mf < 4; mf++) {
                int r  = wm * 64 + mf * 16 + (lane & 15);
                int lc = ks * 2 + (lane >> 4);
                LDSM_X4(a[mf][0], a[mf][1], a[mf][2], a[mf][3],
                        abase + r * 64 + 16 * (lc ^ ((r >> 1) & 3)));
            }
            uint32_t b[2][4];
#pragma unroll
            for (int np = 0; np < 2; np++) {
                int k  = ks * 16 + ((lane >> 3) & 1) * 8 + (lane & 7);
                int nl = wn * 32 + np * 16 + (lane >> 4) * 8;
                LDSM_X4_T(b[np][0], b[np][1], b[np][2], b[np][3],
                          abase + 8192 + k * 128 + 16 * ((nl >> 3) ^ (k & 7)));
            }
#pragma unroll
            for (int mf = 0; mf < 4; mf++)
#pragma unroll
                for (int nf = 0; nf < 4; nf++)
                    MMA_F16(acc[mf][nf], a[mf], b[nf >> 1][(nf & 1) * 2],
                            b[nf >> 1][(nf & 1) * 2 + 1]);
        }
    }

#pragma unroll
    for (int mf = 0; mf < 4; mf++) {
        int r0 = m0 + wm * 64 + mf * 16 + (lane >> 2);
        int r1 = r0 + 8;
        bool ok0 = r0 < mmax, ok1 = r1 < mmax;
        float w0 = ok0 ? g_slot_w[r0] : 0.f;
        float w1 = ok1 ? g_slot_w[r1] : 0.f;
        int tok0 = ok0 ? g_slot_token[r0] : 0;
        int tok1 = ok1 ? g_slot_token[r1] : 0;
#pragma unroll
        for (int nf = 0; nf < 4; nf++) {
            int col = nb * BN + wn * 32 + nf * 8 + (lane & 3) * 2;
            if (ok0) {
                float* p = out + (size_t)tok0 * D_DIM + col;
                red_add(p,     acc[mf][nf][0] * w0);
                red_add(p + 1, acc[mf][nf][1] * w0);
            }
            if (ok1) {
                float* p = out + (size_t)tok1 * D_DIM + col;
                red_add(p,     acc[mf][nf][2] * w1);
                red_add(p + 1, acc[mf][nf][3] * w1);
            }
        }
    }
}

// ================= aux (side stream) =================
__global__ void aux_kernel(float* __restrict__ out, int out_size) {
    __shared__ float red[256];
    __shared__ float esum[E_NUM];
    float part[E_NUM];
#pragma unroll
    for (int e = 0; e < E_NUM; e++) part[e] = 0.f;
    for (int t = threadIdx.x; t < T_TOK; t += 256)
#pragma unroll
        for (int e = 0; e < E_NUM; e++) part[e] += g_probs[t * E_NUM + e];
    for (int e = 0; e < E_NUM; e++) {
        red[threadIdx.x] = part[e];
        __syncthreads();
        for (int off = 128; off > 0; off >>= 1) {
            if (threadIdx.x < off) red[threadIdx.x] += red[threadIdx.x + off];
            __syncthreads();
        }
        if (threadIdx.x == 0) esum[e] = red[0];
        __syncthreads();
    }
    if (threadIdx.x == 0) {
        float aux = 0.f;
        for (int e = 0; e < E_NUM; e++)
            aux += ((float)g_counts[e] / (float)T_TOK) * (esum[e] / (float)T_TOK);
        aux *= 0.01f * (float)E_NUM;
        if (out_size > T_TOK * D_DIM) out[(size_t)T_TOK * D_DIM] = aux;
    }
}

// ================= launch =================
extern "C" void kernel_launch(void* const* d_in, const int* in_sizes, int n_in,
                              void* d_out, int out_size) {
    const float* x      = (const float*)d_in[0];
    const float* gate_w = (const float*)d_in[1];
    const float* Wg     = (const float*)d_in[2];
    const float* Wu     = (const float*)d_in[3];
    const float* Wd     = (const float*)d_in[4];
    float* out = (float*)d_out;

    cudaFuncSetAttribute(ffn1_kernel, cudaFuncAttributeMaxDynamicSharedMemorySize,
                         NSTAGE * 16384);
    cudaFuncSetAttribute(ffn2_kernel, cudaFuncAttributeMaxDynamicSharedMemorySize,
                         NSTAGE * 12288);

    cudaStream_t sA;
    cudaStreamCreateWithFlags(&sA, cudaStreamNonBlocking);
    cudaEvent_t evFork, evW0, evW1, evZ, evPre, evF0, evB;
    cudaEventCreateWithFlags(&evFork, cudaEventDisableTiming);
    cudaEventCreateWithFlags(&evW0,  cudaEventDisableTiming);
    cudaEventCreateWithFlags(&evW1,  cudaEventDisableTiming);
    cudaEventCreateWithFlags(&evZ,   cudaEventDisableTiming);
    cudaEventCreateWithFlags(&evPre, cudaEventDisableTiming);
    cudaEventCreateWithFlags(&evF0,  cudaEventDisableTiming);
    cudaEventCreateWithFlags(&evB,   cudaEventDisableTiming);

    // fork side stream FROM the capture origin stream
    cudaEventRecord(evFork, 0);
    cudaStreamWaitEvent(sA, evFork, 0);

    // side stream: conv half 0, conv half 1, Wd convert + out zero
    conv_wgu_kernel<<<2 * HBLK, 256, 0, sA>>>((const float4*)Wg, (const float4*)Wu, 0);
    cudaEventRecord(evW0, sA);
    conv_wgu_kernel<<<2 * HBLK, 256, 0, sA>>>((const float4*)Wg, (const float4*)Wu, HEXP);
    cudaEventRecord(evW1, sA);
    int wz_blocks = (int)((WQ4 + ZQ4 + 255) / 256);
    wdzero_kernel<<<wz_blocks, 256, 0, sA>>>((const float4*)Wd, (float4*)out);
    cudaEventRecord(evZ, sA);

    // main stream: router chain (hidden under the converts)
    gwt_kernel<<<E_NUM * D_DIM / 256, 256>>>(gate_w);
    router_kernel<<<T_TOK / 8, 256>>>(x);
    offsets_kernel<<<1, 32>>>();
    scatter_pos_kernel<<<(NSLOT + 255) / 256, 256>>>();
    cudaEventRecord(evPre, 0);

    // aux rides the side stream (needs router output only; writes out[T*D] only)
    cudaStreamWaitEvent(sA, evPre, 0);
    aux_kernel<<<1, 256, 0, sA>>>(out, out_size);

    dim3 g1(HMT, I_DIM / BN);   // 136 x 44
    dim3 g2(HMT, D_DIM / BN);   // 136 x 16, mb fastest (R15 order)

    // FFN1 half 0, then half 1 on main stream
    cudaStreamWaitEvent(0, evW0, 0);
    ffn1_kernel<<<g1, 128, NSTAGE * 16384>>>(0, HEXP);
    cudaEventRecord(evF0, 0);
    cudaStreamWaitEvent(0, evW1, 0);
    ffn1_kernel<<<g1, 128, NSTAGE * 16384>>>(HEXP, E_NUM);

    // FFN2 half 0 overlaps FFN1 half 1 on the side stream
    // (needs: H rows of half 0 = evF0; Wd + zeroed out = earlier on sA)
    cudaStreamWaitEvent(sA, evF0, 0);
    ffn2_kernel<<<g2, 128, NSTAGE * 12288, sA>>>(out, 0, HEXP);
    cudaEventRecord(evB, sA);

    // FFN2 half 1 on main (after FFN1 half 1; needs Wd + zeroed out)
    cudaStreamWaitEvent(0, evZ, 0);
    ffn2_kernel<<<g2, 128, NSTAGE * 12288>>>(out, HEXP, E_NUM);

    // join side stream back into the origin stream
    cudaStreamWaitEvent(0, evB, 0);
}